// round 1
// baseline (speedup 1.0000x reference)
#include <cuda_runtime.h>
#include <cuda_bf16.h>

// Problem: single-head causal attention.
// x:[256,256,512] f32; Wk/Wq/Wv:[512,64]; bk/bq/bv:[64]; out:[256,256,64] f32.
// Stage 1: qkv_gemm (3 GEMMs, fused bias) -> __device__ scratch g_q/g_k/g_v.
// Stage 2: attn_kernel: one CTA per batch, K/V in 128KB dynamic smem,
//          one query row per thread, online softmax with lazy rescale.

#define BATCH 256
#define SEQ   256
#define EMBD  512
#define HEAD  64
#define ROWS  (BATCH * SEQ)      // 65536

__device__ float g_q[ROWS * HEAD];
__device__ float g_k[ROWS * HEAD];
__device__ float g_v[ROWS * HEAD];

// ---------------------------------------------------------------------------
// Stage 1: out[r][c] = sum_k x[r][k]*W[k][c] + bias[c]
// Tile: 128(M) x 64(N) x 32(K); 128 threads; 8x8 micro-tile per thread.
// x tile stored transposed+padded in smem: conflict-free scalar a-loads.
// ---------------------------------------------------------------------------
#define GM 128
#define GN 64
#define GK 32

__global__ __launch_bounds__(128) void qkv_gemm(
    const float* __restrict__ x,
    const float* __restrict__ Wk, const float* __restrict__ bk,
    const float* __restrict__ Wq, const float* __restrict__ bq,
    const float* __restrict__ Wv, const float* __restrict__ bv)
{
    __shared__ float xs[GK][GM + 1];   // 32 x 129 (padded: conflict-free)
    __shared__ float ws[GK][GN];       // 32 x 64

    const float* W;
    const float* bias;
    float* out;
    if (blockIdx.y == 0)      { W = Wk; bias = bk; out = g_k; }
    else if (blockIdx.y == 1) { W = Wq; bias = bq; out = g_q; }
    else                      { W = Wv; bias = bv; out = g_v; }

    const int tid  = threadIdx.x;       // 0..127
    const int row0 = blockIdx.x * GM;
    const int tr   = tid >> 3;          // 0..15 -> rows tr*8..tr*8+7
    const int tc   = tid & 7;           // 0..7  -> cols tc*8..tc*8+7

    float acc[8][8];
#pragma unroll
    for (int i = 0; i < 8; i++)
#pragma unroll
        for (int j = 0; j < 8; j++) acc[i][j] = 0.f;

    for (int k0 = 0; k0 < EMBD; k0 += GK) {
        // Load x tile (128x32) as float4, store transposed (scalar, conflict-free).
#pragma unroll
        for (int i = 0; i < 8; i++) {
            int f  = tid + i * 128;     // float4 index 0..1023
            int r  = f >> 3;            // row 0..127
            int c4 = f & 7;             // which float4 in the row
            float4 v = *(const float4*)&x[(size_t)(row0 + r) * EMBD + k0 + c4 * 4];
            xs[c4 * 4 + 0][r] = v.x;
            xs[c4 * 4 + 1][r] = v.y;
            xs[c4 * 4 + 2][r] = v.z;
            xs[c4 * 4 + 3][r] = v.w;
        }
        // Load W tile (32x64) as float4.
#pragma unroll
        for (int i = 0; i < 4; i++) {
            int f  = tid + i * 128;     // 0..511
            int r  = f >> 4;            // 0..31
            int c4 = f & 15;            // 0..15
            *(float4*)&ws[r][c4 * 4] =
                *(const float4*)&W[(size_t)(k0 + r) * HEAD + c4 * 4];
        }
        __syncthreads();

#pragma unroll
        for (int kk = 0; kk < GK; kk++) {
            float a[8], b[8];
#pragma unroll
            for (int i = 0; i < 8; i++) a[i] = xs[kk][tr * 8 + i];
            float4 b0 = *(const float4*)&ws[kk][tc * 8];
            float4 b1 = *(const float4*)&ws[kk][tc * 8 + 4];
            b[0] = b0.x; b[1] = b0.y; b[2] = b0.z; b[3] = b0.w;
            b[4] = b1.x; b[5] = b1.y; b[6] = b1.z; b[7] = b1.w;
#pragma unroll
            for (int i = 0; i < 8; i++)
#pragma unroll
                for (int j = 0; j < 8; j++)
                    acc[i][j] += a[i] * b[j];
        }
        __syncthreads();
    }

    // Epilogue: add bias, write.
#pragma unroll
    for (int i = 0; i < 8; i++) {
        int r = row0 + tr * 8 + i;
#pragma unroll
        for (int j = 0; j < 8; j += 4) {
            int c = tc * 8 + j;
            float4 o;
            o.x = acc[i][j + 0] + bias[c + 0];
            o.y = acc[i][j + 1] + bias[c + 1];
            o.z = acc[i][j + 2] + bias[c + 2];
            o.w = acc[i][j + 3] + bias[c + 3];
            *(float4*)&out[(size_t)r * HEAD + c] = o;
        }
    }
}

// ---------------------------------------------------------------------------
// Stage 2: attention. One CTA per batch; 256 threads = one query row each.
// K,V for the batch live in 128KB dynamic smem (broadcast reads).
// Causal loop truncated per warp: warp w only scans s < 32*(w+1).
// Online softmax with lazy rescale (rescale only when running max improves).
// ---------------------------------------------------------------------------
__global__ __launch_bounds__(256) void attn_kernel(float* __restrict__ out)
{
    extern __shared__ float smem[];
    float* sK = smem;                  // 256*64
    float* sV = smem + SEQ * HEAD;     // 256*64

    const int b   = blockIdx.x;
    const int tid = threadIdx.x;
    const int t   = tid;               // query row

    // Cooperative load of K and V tiles (coalesced float4).
    const float4* kg = (const float4*)(g_k + (size_t)b * SEQ * HEAD);
    const float4* vg = (const float4*)(g_v + (size_t)b * SEQ * HEAD);
    float4* sK4 = (float4*)sK;
    float4* sV4 = (float4*)sV;
    for (int i = tid; i < SEQ * HEAD / 4; i += 256) {
        sK4[i] = kg[i];
        sV4[i] = vg[i];
    }

    // q row into registers.
    float4 qr[16];
    const float4* qg = (const float4*)(g_q + (size_t)b * SEQ * HEAD + (size_t)t * HEAD);
#pragma unroll
    for (int i = 0; i < 16; i++) qr[i] = qg[i];

    __syncthreads();

    const int s_end = ((t >> 5) + 1) << 5;   // covers all s <= t within the warp
    float m = -1e30f;
    float l = 0.f;
    float4 acc[16];
#pragma unroll
    for (int i = 0; i < 16; i++) acc[i] = make_float4(0.f, 0.f, 0.f, 0.f);

    for (int s = 0; s < s_end; ++s) {
        const float4* ks4 = (const float4*)(sK + s * HEAD);
        float4 d = make_float4(0.f, 0.f, 0.f, 0.f);
#pragma unroll
        for (int i = 0; i < 16; i++) {
            float4 kk = ks4[i];
            d.x += qr[i].x * kk.x;
            d.y += qr[i].y * kk.y;
            d.z += qr[i].z * kk.z;
            d.w += qr[i].w * kk.w;
        }
        float score = (d.x + d.y + d.z + d.w) * 0.125f;   // 1/sqrt(64)

        if (s <= t) {
            if (score > m) {
                float corr = __expf(m - score);           // exp(-huge) -> 0 first time
                m = score;
                l *= corr;
#pragma unroll
                for (int i = 0; i < 16; i++) {
                    acc[i].x *= corr; acc[i].y *= corr;
                    acc[i].z *= corr; acc[i].w *= corr;
                }
            }
            float p = __expf(score - m);
            l += p;
            const float4* vs4 = (const float4*)(sV + s * HEAD);
#pragma unroll
            for (int i = 0; i < 16; i++) {
                float4 vv = vs4[i];
                acc[i].x += p * vv.x;
                acc[i].y += p * vv.y;
                acc[i].z += p * vv.z;
                acc[i].w += p * vv.w;
            }
        }
    }

    const float inv = 1.f / l;
    float4* og = (float4*)(out + (size_t)b * SEQ * HEAD + (size_t)t * HEAD);
#pragma unroll
    for (int i = 0; i < 16; i++) {
        float4 o;
        o.x = acc[i].x * inv;
        o.y = acc[i].y * inv;
        o.z = acc[i].z * inv;
        o.w = acc[i].w * inv;
        og[i] = o;
    }
}

// ---------------------------------------------------------------------------
extern "C" void kernel_launch(void* const* d_in, const int* in_sizes, int n_in,
                              void* d_out, int out_size)
{
    const float* x  = (const float*)d_in[0];
    const float* Wk = (const float*)d_in[1];
    const float* bk = (const float*)d_in[2];
    const float* Wq = (const float*)d_in[3];
    const float* bq = (const float*)d_in[4];
    const float* Wv = (const float*)d_in[5];
    const float* bv = (const float*)d_in[6];
    float* out = (float*)d_out;

    (void)in_sizes; (void)n_in; (void)out_size;

    dim3 ggrid(ROWS / GM, 3);
    qkv_gemm<<<ggrid, 128>>>(x, Wk, bk, Wq, bq, Wv, bv);

    const int smem_bytes = 2 * SEQ * HEAD * sizeof(float);   // 128 KB
    cudaFuncSetAttribute(attn_kernel,
                         cudaFuncAttributeMaxDynamicSharedMemorySize, smem_bytes);
    attn_kernel<<<BATCH, 256, smem_bytes>>>(out);
}

// round 3
// speedup vs baseline: 1.6372x; 1.6372x over previous
#include <cuda_runtime.h>
#include <cuda_bf16.h>
#include <cstdint>

#define BATCH 256
#define SEQ   256
#define EMBD  512
#define HEAD  64
#define ROWS  (BATCH * SEQ)      // 65536

__device__ float g_q[ROWS * HEAD];
__device__ float g_k[ROWS * HEAD];
__device__ float g_v[ROWS * HEAD];

// ===========================================================================
// Helpers
// ===========================================================================
__device__ __forceinline__ float tf32_rna(float x) {
    float y;
    asm("cvt.rna.tf32.f32 %0, %1;" : "=f"(y) : "f"(x));
    return y;
}

__device__ __forceinline__ void mma_tf32(float& c0, float& c1, float& c2, float& c3,
                                         uint32_t a0, uint32_t a1, uint32_t a2, uint32_t a3,
                                         uint32_t b0, uint32_t b1) {
    asm volatile(
        "mma.sync.aligned.m16n8k8.row.col.f32.tf32.tf32.f32 "
        "{%0,%1,%2,%3}, {%4,%5,%6,%7}, {%8,%9}, {%0,%1,%2,%3};"
        : "+f"(c0), "+f"(c1), "+f"(c2), "+f"(c3)
        : "r"(a0), "r"(a1), "r"(a2), "r"(a3), "r"(b0), "r"(b1));
}

// ===========================================================================
// Stage 1: QKV projection via mma.sync tf32.
// CTA: 128 threads / 4 warps. Tile M=128, N=64, K-chunk=32. One matrix per
// CTA (grid m-fastest so the 3 CTAs of one row-tile co-reside -> x L2 reuse).
//
// Smem holds fragment-permuted tiles:
//  A region per (warp, mtile, kstep): 32 lanes x 16B (a0..a3 contiguous),
//    xor-swizzled by (ks<<5)  -> frag load = 1 x LDS.128, conflict-free.
//  B region per (kstep, ntile): 32 lanes x 8B (b0,b1 contiguous),
//    xor-swizzled by ((nt&3)<<5 | (nt>>2)<<3) -> frag load = 1 x LDS.64.
// ===========================================================================
#define KCHUNK 32
#define NCHNK  (EMBD / KCHUNK)   // 16
#define SM_B_OFF   16384
#define SM_BIAS    (16384 + 8192)
#define SM_TOTAL   (SM_BIAS + 256)

__global__ __launch_bounds__(128) void qkv_gemm_mma(
    const float* __restrict__ x,
    const float* __restrict__ Wk, const float* __restrict__ Wq, const float* __restrict__ Wv,
    const float* __restrict__ bk, const float* __restrict__ bq, const float* __restrict__ bv)
{
    __shared__ __align__(16) char sm[SM_TOTAL];

    const int m    = blockIdx.x % 3;
    const int tile = blockIdx.x / 3;
    const int row0 = tile * 128;
    const int tid  = threadIdx.x;
    const int w    = tid >> 5;
    const int lane = tid & 31;

    const float* W    = (m == 0) ? Wk : (m == 1) ? Wq : Wv;
    const float* bias = (m == 0) ? bk : (m == 1) ? bq : bv;
    float* out        = (m == 0) ? g_k : (m == 1) ? g_q : g_v;

    if (tid < 64) ((float*)(sm + SM_BIAS))[tid] = bias[tid];

    float acc[2][8][4];
#pragma unroll
    for (int mt = 0; mt < 2; mt++)
#pragma unroll
        for (int nt = 0; nt < 8; nt++)
#pragma unroll
            for (int j = 0; j < 4; j++) acc[mt][nt][j] = 0.f;

    float4 pa[8];   // prefetched A (x) chunk
    float4 pb[4];   // prefetched B (W) chunk

    // prologue: load chunk 0
#pragma unroll
    for (int i = 0; i < 8; i++) {
        int f4 = tid + i * 128;
        int r = f4 >> 3, c4 = f4 & 7;
        pa[i] = *(const float4*)&x[(size_t)(row0 + r) * EMBD + c4 * 4];
    }
#pragma unroll
    for (int i = 0; i < 4; i++) {
        int f4 = tid + i * 128;
        int k = f4 >> 4, n4 = f4 & 15;
        pb[i] = *(const float4*)&W[(size_t)k * HEAD + n4 * 4];
    }

    for (int c = 0; c < NCHNK; ++c) {
        if (c > 0) __syncthreads();   // prev chunk's frag loads done

        // ---- store A chunk (fragment-permuted, tf32-rounded) ----
#pragma unroll
        for (int i = 0; i < 8; i++) {
            int f4 = tid + i * 128;
            int r = f4 >> 3, c4 = f4 & 7;
            int ks = c4 >> 1;
            int rl = r & 15;
            int regb = ((c4 & 1) << 1) | (rl >> 3);
            int lbase = (rl & 7) << 2;
            int region = (((r >> 4) * 4) + ks) * 512;   // (w*2+mt)*4+ks, r>>4 = w*2+mt
            float e[4] = {tf32_rna(pa[i].x), tf32_rna(pa[i].y),
                          tf32_rna(pa[i].z), tf32_rna(pa[i].w)};
#pragma unroll
            for (int j = 0; j < 4; j++) {
                int l = lbase | j;
                *(float*)(sm + region + (((l * 16) ^ (ks << 5)) + regb * 4)) = e[j];
            }
        }
        // ---- store B chunk ----
#pragma unroll
        for (int i = 0; i < 4; i++) {
            int f4 = tid + i * 128;
            int k = f4 >> 4, n4 = f4 & 15;
            int ks = k >> 3, kin = k & 7;
            int regb = kin >> 2, kin3 = kin & 3;
            int nt = n4 >> 1, nb = (n4 & 1) * 4;
            int bsw = ((nt & 3) << 5) | ((nt >> 2) << 3);
            int region = SM_B_OFF + (ks * 8 + nt) * 256;
            float e[4] = {tf32_rna(pb[i].x), tf32_rna(pb[i].y),
                          tf32_rna(pb[i].z), tf32_rna(pb[i].w)};
#pragma unroll
            for (int j = 0; j < 4; j++) {
                int l = ((nb + j) << 2) | kin3;
                *(float*)(sm + region + (((l * 8) ^ bsw) + regb * 4)) = e[j];
            }
        }
        __syncthreads();

        // ---- prefetch next chunk (overlaps with MMA section below) ----
        if (c + 1 < NCHNK) {
            const int k0 = (c + 1) * KCHUNK;
#pragma unroll
            for (int i = 0; i < 8; i++) {
                int f4 = tid + i * 128;
                int r = f4 >> 3, c4 = f4 & 7;
                pa[i] = *(const float4*)&x[(size_t)(row0 + r) * EMBD + k0 + c4 * 4];
            }
#pragma unroll
            for (int i = 0; i < 4; i++) {
                int f4 = tid + i * 128;
                int k = f4 >> 4, n4 = f4 & 15;
                pb[i] = *(const float4*)&W[(size_t)(k0 + k) * HEAD + n4 * 4];
            }
        }

        // ---- MMA section ----
#pragma unroll
        for (int ks = 0; ks < 4; ks++) {
            uint4 afr[2];
#pragma unroll
            for (int mt = 0; mt < 2; mt++)
                afr[mt] = *(const uint4*)(sm + ((w * 2 + mt) * 4 + ks) * 512 +
                                          ((lane * 16) ^ (ks << 5)));
            uint2 bfr[8];
#pragma unroll
            for (int nt = 0; nt < 8; nt++) {
                int bsw = ((nt & 3) << 5) | ((nt >> 2) << 3);
                bfr[nt] = *(const uint2*)(sm + SM_B_OFF + (ks * 8 + nt) * 256 +
                                          ((lane * 8) ^ bsw));
            }
#pragma unroll
            for (int nt = 0; nt < 8; nt++)
#pragma unroll
                for (int mt = 0; mt < 2; mt++)
                    mma_tf32(acc[mt][nt][0], acc[mt][nt][1], acc[mt][nt][2], acc[mt][nt][3],
                             afr[mt].x, afr[mt].y, afr[mt].z, afr[mt].w,
                             bfr[nt].x, bfr[nt].y);
        }
    }

    // ---- epilogue: +bias, store (two float2 per (mt,nt) per thread) ----
    const float* sbias = (const float*)(sm + SM_BIAS);
#pragma unroll
    for (int mt = 0; mt < 2; mt++) {
        int r0 = row0 + w * 32 + mt * 16 + (lane >> 2);
#pragma unroll
        for (int nt = 0; nt < 8; nt++) {
            int col = nt * 8 + (lane & 3) * 2;
            float b0 = sbias[col], b1 = sbias[col + 1];
            float2 v0 = make_float2(acc[mt][nt][0] + b0, acc[mt][nt][1] + b1);
            float2 v1 = make_float2(acc[mt][nt][2] + b0, acc[mt][nt][3] + b1);
            *(float2*)&out[(size_t)r0 * HEAD + col] = v0;
            *(float2*)&out[(size_t)(r0 + 8) * HEAD + col] = v1;
        }
    }
}

// ===========================================================================
// Stage 2: attention (unchanged): one CTA per batch, K/V in 128KB smem,
// one query row per thread, online softmax, warp-truncated causal loop.
// ===========================================================================
__global__ __launch_bounds__(256) void attn_kernel(float* __restrict__ out)
{
    extern __shared__ float fsmem[];
    float* sK = fsmem;
    float* sV = fsmem + SEQ * HEAD;

    const int b   = blockIdx.x;
    const int tid = threadIdx.x;
    const int t   = tid;

    const float4* kg = (const float4*)(g_k + (size_t)b * SEQ * HEAD);
    const float4* vg = (const float4*)(g_v + (size_t)b * SEQ * HEAD);
    float4* sK4 = (float4*)sK;
    float4* sV4 = (float4*)sV;
    for (int i = tid; i < SEQ * HEAD / 4; i += 256) {
        sK4[i] = kg[i];
        sV4[i] = vg[i];
    }

    float4 qr[16];
    const float4* qg = (const float4*)(g_q + (size_t)b * SEQ * HEAD + (size_t)t * HEAD);
#pragma unroll
    for (int i = 0; i < 16; i++) qr[i] = qg[i];

    __syncthreads();

    const int s_end = ((t >> 5) + 1) << 5;
    float m = -1e30f;
    float l = 0.f;
    float4 acc[16];
#pragma unroll
    for (int i = 0; i < 16; i++) acc[i] = make_float4(0.f, 0.f, 0.f, 0.f);

    for (int s = 0; s < s_end; ++s) {
        const float4* ks4 = (const float4*)(sK + s * HEAD);
        float4 d = make_float4(0.f, 0.f, 0.f, 0.f);
#pragma unroll
        for (int i = 0; i < 16; i++) {
            float4 kk = ks4[i];
            d.x += qr[i].x * kk.x;
            d.y += qr[i].y * kk.y;
            d.z += qr[i].z * kk.z;
            d.w += qr[i].w * kk.w;
        }
        float score = (d.x + d.y + d.z + d.w) * 0.125f;

        if (s <= t) {
            if (score > m) {
                float corr = __expf(m - score);
                m = score;
                l *= corr;
#pragma unroll
                for (int i = 0; i < 16; i++) {
                    acc[i].x *= corr; acc[i].y *= corr;
                    acc[i].z *= corr; acc[i].w *= corr;
                }
            }
            float p = __expf(score - m);
            l += p;
            const float4* vs4 = (const float4*)(sV + s * HEAD);
#pragma unroll
            for (int i = 0; i < 16; i++) {
                float4 vv = vs4[i];
                acc[i].x += p * vv.x;
                acc[i].y += p * vv.y;
                acc[i].z += p * vv.z;
                acc[i].w += p * vv.w;
            }
        }
    }

    const float inv = 1.f / l;
    float4* og = (float4*)(out + (size_t)b * SEQ * HEAD + (size_t)t * HEAD);
#pragma unroll
    for (int i = 0; i < 16; i++) {
        float4 o;
        o.x = acc[i].x * inv;
        o.y = acc[i].y * inv;
        o.z = acc[i].z * inv;
        o.w = acc[i].w * inv;
        og[i] = o;
    }
}

// ===========================================================================
extern "C" void kernel_launch(void* const* d_in, const int* in_sizes, int n_in,
                              void* d_out, int out_size)
{
    const float* x  = (const float*)d_in[0];
    const float* Wk = (const float*)d_in[1];
    const float* bk = (const float*)d_in[2];
    const float* Wq = (const float*)d_in[3];
    const float* bq = (const float*)d_in[4];
    const float* Wv = (const float*)d_in[5];
    const float* bv = (const float*)d_in[6];
    float* out = (float*)d_out;
    (void)in_sizes; (void)n_in; (void)out_size;

    qkv_gemm_mma<<<(ROWS / 128) * 3, 128>>>(x, Wk, Wq, Wv, bk, bq, bv);

    const int smem_bytes = 2 * SEQ * HEAD * sizeof(float);   // 128 KB
    cudaFuncSetAttribute(attn_kernel,
                         cudaFuncAttributeMaxDynamicSharedMemorySize, smem_bytes);
    attn_kernel<<<BATCH, 256, smem_bytes>>>(out);
}

// round 4
// speedup vs baseline: 2.3399x; 1.4292x over previous
#include <cuda_runtime.h>
#include <cuda_bf16.h>
#include <cstdint>

#define BATCH 256
#define SEQ   256
#define EMBD  512
#define HEAD  64
#define ROWS  (BATCH * SEQ)      // 65536

__device__ float g_q[ROWS * HEAD];
__device__ float g_k[ROWS * HEAD];
__device__ float g_v[ROWS * HEAD];

// ===========================================================================
// Helpers
// ===========================================================================
__device__ __forceinline__ float tf32_rna(float x) {
    float y;
    asm("cvt.rna.tf32.f32 %0, %1;" : "=f"(y) : "f"(x));
    return y;
}

__device__ __forceinline__ void mma_tf32(float& c0, float& c1, float& c2, float& c3,
                                         uint32_t a0, uint32_t a1, uint32_t a2, uint32_t a3,
                                         uint32_t b0, uint32_t b1) {
    asm volatile(
        "mma.sync.aligned.m16n8k8.row.col.f32.tf32.tf32.f32 "
        "{%0,%1,%2,%3}, {%4,%5,%6,%7}, {%8,%9}, {%0,%1,%2,%3};"
        : "+f"(c0), "+f"(c1), "+f"(c2), "+f"(c3)
        : "r"(a0), "r"(a1), "r"(a2), "r"(a3), "r"(b0), "r"(b1));
}

// ===========================================================================
// Stage 1: QKV projection via mma.sync tf32 (unchanged from R2).
// ===========================================================================
#define KCHUNK 32
#define NCHNK  (EMBD / KCHUNK)   // 16
#define SM_B_OFF   16384
#define SM_BIAS    (16384 + 8192)
#define SM_TOTAL   (SM_BIAS + 256)

__global__ __launch_bounds__(128) void qkv_gemm_mma(
    const float* __restrict__ x,
    const float* __restrict__ Wk, const float* __restrict__ Wq, const float* __restrict__ Wv,
    const float* __restrict__ bk, const float* __restrict__ bq, const float* __restrict__ bv)
{
    __shared__ __align__(16) char sm[SM_TOTAL];

    const int m    = blockIdx.x % 3;
    const int tile = blockIdx.x / 3;
    const int row0 = tile * 128;
    const int tid  = threadIdx.x;
    const int w    = tid >> 5;
    const int lane = tid & 31;

    const float* W    = (m == 0) ? Wk : (m == 1) ? Wq : Wv;
    const float* bias = (m == 0) ? bk : (m == 1) ? bq : bv;
    float* out        = (m == 0) ? g_k : (m == 1) ? g_q : g_v;

    if (tid < 64) ((float*)(sm + SM_BIAS))[tid] = bias[tid];

    float acc[2][8][4];
#pragma unroll
    for (int mt = 0; mt < 2; mt++)
#pragma unroll
        for (int nt = 0; nt < 8; nt++)
#pragma unroll
            for (int j = 0; j < 4; j++) acc[mt][nt][j] = 0.f;

    float4 pa[8];
    float4 pb[4];

#pragma unroll
    for (int i = 0; i < 8; i++) {
        int f4 = tid + i * 128;
        int r = f4 >> 3, c4 = f4 & 7;
        pa[i] = *(const float4*)&x[(size_t)(row0 + r) * EMBD + c4 * 4];
    }
#pragma unroll
    for (int i = 0; i < 4; i++) {
        int f4 = tid + i * 128;
        int k = f4 >> 4, n4 = f4 & 15;
        pb[i] = *(const float4*)&W[(size_t)k * HEAD + n4 * 4];
    }

    for (int c = 0; c < NCHNK; ++c) {
        if (c > 0) __syncthreads();

#pragma unroll
        for (int i = 0; i < 8; i++) {
            int f4 = tid + i * 128;
            int r = f4 >> 3, c4 = f4 & 7;
            int ks = c4 >> 1;
            int rl = r & 15;
            int regb = ((c4 & 1) << 1) | (rl >> 3);
            int lbase = (rl & 7) << 2;
            int region = (((r >> 4) * 4) + ks) * 512;
            float e[4] = {tf32_rna(pa[i].x), tf32_rna(pa[i].y),
                          tf32_rna(pa[i].z), tf32_rna(pa[i].w)};
#pragma unroll
            for (int j = 0; j < 4; j++) {
                int l = lbase | j;
                *(float*)(sm + region + (((l * 16) ^ (ks << 5)) + regb * 4)) = e[j];
            }
        }
#pragma unroll
        for (int i = 0; i < 4; i++) {
            int f4 = tid + i * 128;
            int k = f4 >> 4, n4 = f4 & 15;
            int ks = k >> 3, kin = k & 7;
            int regb = kin >> 2, kin3 = kin & 3;
            int nt = n4 >> 1, nb = (n4 & 1) * 4;
            int bsw = ((nt & 3) << 5) | ((nt >> 2) << 3);
            int region = SM_B_OFF + (ks * 8 + nt) * 256;
            float e[4] = {tf32_rna(pb[i].x), tf32_rna(pb[i].y),
                          tf32_rna(pb[i].z), tf32_rna(pb[i].w)};
#pragma unroll
            for (int j = 0; j < 4; j++) {
                int l = ((nb + j) << 2) | kin3;
                *(float*)(sm + region + (((l * 8) ^ bsw) + regb * 4)) = e[j];
            }
        }
        __syncthreads();

        if (c + 1 < NCHNK) {
            const int k0 = (c + 1) * KCHUNK;
#pragma unroll
            for (int i = 0; i < 8; i++) {
                int f4 = tid + i * 128;
                int r = f4 >> 3, c4 = f4 & 7;
                pa[i] = *(const float4*)&x[(size_t)(row0 + r) * EMBD + k0 + c4 * 4];
            }
#pragma unroll
            for (int i = 0; i < 4; i++) {
                int f4 = tid + i * 128;
                int k = f4 >> 4, n4 = f4 & 15;
                pb[i] = *(const float4*)&W[(size_t)(k0 + k) * HEAD + n4 * 4];
            }
        }

#pragma unroll
        for (int ks = 0; ks < 4; ks++) {
            uint4 afr[2];
#pragma unroll
            for (int mt = 0; mt < 2; mt++)
                afr[mt] = *(const uint4*)(sm + ((w * 2 + mt) * 4 + ks) * 512 +
                                          ((lane * 16) ^ (ks << 5)));
            uint2 bfr[8];
#pragma unroll
            for (int nt = 0; nt < 8; nt++) {
                int bsw = ((nt & 3) << 5) | ((nt >> 2) << 3);
                bfr[nt] = *(const uint2*)(sm + SM_B_OFF + (ks * 8 + nt) * 256 +
                                          ((lane * 8) ^ bsw));
            }
#pragma unroll
            for (int nt = 0; nt < 8; nt++)
#pragma unroll
                for (int mt = 0; mt < 2; mt++)
                    mma_tf32(acc[mt][nt][0], acc[mt][nt][1], acc[mt][nt][2], acc[mt][nt][3],
                             afr[mt].x, afr[mt].y, afr[mt].z, afr[mt].w,
                             bfr[nt].x, bfr[nt].y);
        }
    }

    const float* sbias = (const float*)(sm + SM_BIAS);
#pragma unroll
    for (int mt = 0; mt < 2; mt++) {
        int r0 = row0 + w * 32 + mt * 16 + (lane >> 2);
#pragma unroll
        for (int nt = 0; nt < 8; nt++) {
            int col = nt * 8 + (lane & 3) * 2;
            float b0 = sbias[col], b1 = sbias[col + 1];
            float2 v0 = make_float2(acc[mt][nt][0] + b0, acc[mt][nt][1] + b1);
            float2 v1 = make_float2(acc[mt][nt][2] + b0, acc[mt][nt][3] + b1);
            *(float2*)&out[(size_t)r0 * HEAD + col] = v0;
            *(float2*)&out[(size_t)(r0 + 8) * HEAD + col] = v1;
        }
    }
}

// ===========================================================================
// Stage 2: flash attention via mma.sync tf32.
// CTA = (batch, 128-query block); 8 warps, each owns m16 query rows.
// K packed as B-frags for S=QK^T (n=key, k=hd); V packed as B-frags for
// O=P*V (n=hd, k=key). Both tf32-rounded at pack, 64KB each region array.
// Per warp: key-block loop to its diagonal, online softmax on fragments,
// P S-frag -> A-frag conversion via quad shfl (no smem round trip).
// ===========================================================================
#define ATT_SMEM (2 * SEQ * HEAD * 4)   // 128KB

__global__ __launch_bounds__(256) void attn_mma(float* __restrict__ out)
{
    extern __shared__ char asm_[];
    float* sKp = (float*)asm_;                       // 64KB
    float* sVp = (float*)(asm_ + SEQ * HEAD * 4);    // 64KB

    const int b    = blockIdx.x >> 1;
    const int qb   = blockIdx.x & 1;
    const int tid  = threadIdx.x;
    const int wid  = tid >> 5;
    const int lane = tid & 31;
    const int g    = lane >> 2;      // row within m16 (and +8)
    const int t    = lane & 3;

    // ---- cooperative fragment-pack of K and V (tf32-rounded) ----
    const float* kg = g_k + (size_t)b * SEQ * HEAD;
    const float* vg = g_v + (size_t)b * SEQ * HEAD;
    for (int i = tid; i < SEQ * HEAD / 4; i += 256) {
        int s = i >> 4, h4 = i & 15;
        float4 kv = *(const float4*)&kg[s * HEAD + h4 * 4];
        float* rb = sKp + ((s >> 3) * 8 + (h4 >> 1)) * 64 + ((s & 7) << 3) + (h4 & 1);
        rb[0] = tf32_rna(kv.x); rb[2] = tf32_rna(kv.y);
        rb[4] = tf32_rna(kv.z); rb[6] = tf32_rna(kv.w);

        float4 vv = *(const float4*)&vg[s * HEAD + h4 * 4];
        float* rb2 = sVp + ((s >> 3) * 8 + (h4 >> 1)) * 64 + (h4 & 1) * 32 +
                     ((s & 3) << 1) + ((s >> 2) & 1);
        rb2[0]  = tf32_rna(vv.x); rb2[8]  = tf32_rna(vv.y);
        rb2[16] = tf32_rna(vv.z); rb2[24] = tf32_rna(vv.w);
    }

    // ---- Q A-fragments (register resident) ----
    const int q0 = qb * 128 + wid * 16;
    const float* qg = g_q + ((size_t)b * SEQ + q0) * HEAD;
    uint32_t qa[8][4];
#pragma unroll
    for (int ks = 0; ks < 8; ks++) {
        qa[ks][0] = __float_as_uint(tf32_rna(qg[(size_t)g * HEAD + ks * 8 + t]));
        qa[ks][1] = __float_as_uint(tf32_rna(qg[(size_t)(g + 8) * HEAD + ks * 8 + t]));
        qa[ks][2] = __float_as_uint(tf32_rna(qg[(size_t)g * HEAD + ks * 8 + t + 4]));
        qa[ks][3] = __float_as_uint(tf32_rna(qg[(size_t)(g + 8) * HEAD + ks * 8 + t + 4]));
    }
    __syncthreads();

    float m0 = -1e30f, m1 = -1e30f, l0 = 0.f, l1 = 0.f;
    float o[8][4];
#pragma unroll
    for (int nf = 0; nf < 8; nf++)
#pragma unroll
        for (int j = 0; j < 4; j++) o[nf][j] = 0.f;

    const int kb_hi = q0 >> 6;
    const int src0 = (lane & ~3) | (t >> 1);
    const int src1 = src0 + 2;

    for (int kb = 0; kb <= kb_hi; kb++) {
        // ---- S = Q K^T ----
        float sacc[8][4];
#pragma unroll
        for (int nf = 0; nf < 8; nf++)
#pragma unroll
            for (int j = 0; j < 4; j++) sacc[nf][j] = 0.f;

#pragma unroll
        for (int ks = 0; ks < 8; ks++) {
            uint2 bf[8];
#pragma unroll
            for (int nf = 0; nf < 8; nf++)
                bf[nf] = *(const uint2*)(sKp + ((kb * 8 + nf) * 8 + ks) * 64 + lane * 2);
#pragma unroll
            for (int nf = 0; nf < 8; nf++)
                mma_tf32(sacc[nf][0], sacc[nf][1], sacc[nf][2], sacc[nf][3],
                         qa[ks][0], qa[ks][1], qa[ks][2], qa[ks][3],
                         bf[nf].x, bf[nf].y);
        }

        // ---- scale + causal mask ----
        const float SC = 0.125f;
        if (kb == kb_hi) {
            const int row0 = q0 + g, row1 = row0 + 8;
#pragma unroll
            for (int nf = 0; nf < 8; nf++) {
                int col = kb * 64 + nf * 8 + 2 * t;
                sacc[nf][0] = (col     <= row0) ? sacc[nf][0] * SC : -1e30f;
                sacc[nf][1] = (col + 1 <= row0) ? sacc[nf][1] * SC : -1e30f;
                sacc[nf][2] = (col     <= row1) ? sacc[nf][2] * SC : -1e30f;
                sacc[nf][3] = (col + 1 <= row1) ? sacc[nf][3] * SC : -1e30f;
            }
        } else {
#pragma unroll
            for (int nf = 0; nf < 8; nf++)
#pragma unroll
                for (int j = 0; j < 4; j++) sacc[nf][j] *= SC;
        }

        // ---- online softmax (rows g, g+8) ----
        float mx0 = -1e30f, mx1 = -1e30f;
#pragma unroll
        for (int nf = 0; nf < 8; nf++) {
            mx0 = fmaxf(mx0, fmaxf(sacc[nf][0], sacc[nf][1]));
            mx1 = fmaxf(mx1, fmaxf(sacc[nf][2], sacc[nf][3]));
        }
        mx0 = fmaxf(mx0, __shfl_xor_sync(0xffffffffu, mx0, 1));
        mx0 = fmaxf(mx0, __shfl_xor_sync(0xffffffffu, mx0, 2));
        mx1 = fmaxf(mx1, __shfl_xor_sync(0xffffffffu, mx1, 1));
        mx1 = fmaxf(mx1, __shfl_xor_sync(0xffffffffu, mx1, 2));

        float mn0 = fmaxf(m0, mx0), mn1 = fmaxf(m1, mx1);
        float cr0 = __expf(m0 - mn0), cr1 = __expf(m1 - mn1);
        m0 = mn0; m1 = mn1;

        float s0 = 0.f, s1 = 0.f;
#pragma unroll
        for (int nf = 0; nf < 8; nf++) {
            float p0 = __expf(sacc[nf][0] - m0);
            float p1 = __expf(sacc[nf][1] - m0);
            float p2 = __expf(sacc[nf][2] - m1);
            float p3 = __expf(sacc[nf][3] - m1);
            s0 += p0 + p1; s1 += p2 + p3;
            sacc[nf][0] = tf32_rna(p0); sacc[nf][1] = tf32_rna(p1);
            sacc[nf][2] = tf32_rna(p2); sacc[nf][3] = tf32_rna(p3);
        }
        s0 += __shfl_xor_sync(0xffffffffu, s0, 1);
        s0 += __shfl_xor_sync(0xffffffffu, s0, 2);
        s1 += __shfl_xor_sync(0xffffffffu, s1, 1);
        s1 += __shfl_xor_sync(0xffffffffu, s1, 2);
        l0 = l0 * cr0 + s0;
        l1 = l1 * cr1 + s1;
#pragma unroll
        for (int nf = 0; nf < 8; nf++) {
            o[nf][0] *= cr0; o[nf][1] *= cr0;
            o[nf][2] *= cr1; o[nf][3] *= cr1;
        }

        // ---- O += P V : S-frag -> A-frag via quad shfl, then mma ----
#pragma unroll
        for (int kf = 0; kf < 8; kf++) {
            float v00 = __shfl_sync(0xffffffffu, sacc[kf][0], src0);
            float v01 = __shfl_sync(0xffffffffu, sacc[kf][1], src0);
            float v10 = __shfl_sync(0xffffffffu, sacc[kf][2], src0);
            float v11 = __shfl_sync(0xffffffffu, sacc[kf][3], src0);
            float w00 = __shfl_sync(0xffffffffu, sacc[kf][0], src1);
            float w01 = __shfl_sync(0xffffffffu, sacc[kf][1], src1);
            float w10 = __shfl_sync(0xffffffffu, sacc[kf][2], src1);
            float w11 = __shfl_sync(0xffffffffu, sacc[kf][3], src1);
            uint32_t a0 = __float_as_uint((t & 1) ? v01 : v00);
            uint32_t a1 = __float_as_uint((t & 1) ? v11 : v10);
            uint32_t a2 = __float_as_uint((t & 1) ? w01 : w00);
            uint32_t a3 = __float_as_uint((t & 1) ? w11 : w10);

            uint2 vb[8];
#pragma unroll
            for (int nf = 0; nf < 8; nf++)
                vb[nf] = *(const uint2*)(sVp + ((kb * 8 + kf) * 8 + nf) * 64 + lane * 2);
#pragma unroll
            for (int nf = 0; nf < 8; nf++)
                mma_tf32(o[nf][0], o[nf][1], o[nf][2], o[nf][3],
                         a0, a1, a2, a3, vb[nf].x, vb[nf].y);
        }
    }

    // ---- epilogue ----
    const float il0 = 1.f / l0, il1 = 1.f / l1;
    float* og = out + ((size_t)b * SEQ + q0) * HEAD;
#pragma unroll
    for (int nf = 0; nf < 8; nf++) {
        int col = nf * 8 + 2 * t;
        *(float2*)&og[(size_t)g * HEAD + col] =
            make_float2(o[nf][0] * il0, o[nf][1] * il0);
        *(float2*)&og[(size_t)(g + 8) * HEAD + col] =
            make_float2(o[nf][2] * il1, o[nf][3] * il1);
    }
}

// ===========================================================================
extern "C" void kernel_launch(void* const* d_in, const int* in_sizes, int n_in,
                              void* d_out, int out_size)
{
    const float* x  = (const float*)d_in[0];
    const float* Wk = (const float*)d_in[1];
    const float* bk = (const float*)d_in[2];
    const float* Wq = (const float*)d_in[3];
    const float* bq = (const float*)d_in[4];
    const float* Wv = (const float*)d_in[5];
    const float* bv = (const float*)d_in[6];
    float* out = (float*)d_out;
    (void)in_sizes; (void)n_in; (void)out_size;

    qkv_gemm_mma<<<(ROWS / 128) * 3, 128>>>(x, Wk, Wq, Wv, bk, bq, bv);

    cudaFuncSetAttribute(attn_mma,
                         cudaFuncAttributeMaxDynamicSharedMemorySize, ATT_SMEM);
    attn_mma<<<BATCH * 2, 256, ATT_SMEM>>>(out);
}

// round 5
// speedup vs baseline: 2.9517x; 1.2614x over previous
#include <cuda_runtime.h>
#include <cuda_bf16.h>
#include <cstdint>

#define BATCH 256
#define SEQ   256
#define EMBD  512
#define HEAD  64
#define ROWS  (BATCH * SEQ)      // 65536

__device__ float g_q[ROWS * HEAD];
__device__ float g_k[ROWS * HEAD];
__device__ float g_v[ROWS * HEAD];

// ===========================================================================
// Helpers
// ===========================================================================
__device__ __forceinline__ float tf32_rna(float x) {
    float y;
    asm("cvt.rna.tf32.f32 %0, %1;" : "=f"(y) : "f"(x));
    return y;
}

__device__ __forceinline__ void mma_tf32(float& c0, float& c1, float& c2, float& c3,
                                         uint32_t a0, uint32_t a1, uint32_t a2, uint32_t a3,
                                         uint32_t b0, uint32_t b1) {
    asm volatile(
        "mma.sync.aligned.m16n8k8.row.col.f32.tf32.tf32.f32 "
        "{%0,%1,%2,%3}, {%4,%5,%6,%7}, {%8,%9}, {%0,%1,%2,%3};"
        : "+f"(c0), "+f"(c1), "+f"(c2), "+f"(c3)
        : "r"(a0), "r"(a1), "r"(a2), "r"(a3), "r"(b0), "r"(b1));
}

// ===========================================================================
// Stage 1: fused QKV projection (all 3 matrices per CTA), mma.sync tf32.
// CTA: 256 threads / 8 warps = 4 row-groups x 2 col-groups.
//   warp tile: 32 rows (mt=2 x m16) x 96 cols (12 x n8).
// Tile M=128, N=192 (K|Q|V concatenated), K-chunk=32.
// Double-buffered fragment-packed smem; ONE syncthreads per chunk:
//   [LDG chunk c+1] [MMA on buf] [STS chunk c+1 -> buf^1] [sync]
// ===========================================================================
#define KCHUNK 32
#define NCHNK  (EMBD / KCHUNK)   // 16
#define STAGE_SZ 40960           // 16KB A-frags + 24KB B-frags
#define SG_A(buf)  ((buf) * STAGE_SZ)
#define SG_B(buf)  ((buf) * STAGE_SZ + 16384)
#define SG_BIAS    (2 * STAGE_SZ)            // 192 floats
#define GEMM_SMEM  (SG_BIAS + 768)

__global__ __launch_bounds__(256, 1) void qkv_gemm_mma(
    const float* __restrict__ x,
    const float* __restrict__ Wk, const float* __restrict__ Wq, const float* __restrict__ Wv,
    const float* __restrict__ bk, const float* __restrict__ bq, const float* __restrict__ bv)
{
    extern __shared__ char sm[];

    const int tid  = threadIdx.x;
    const int wid  = tid >> 5;
    const int lane = tid & 31;
    const int rg   = wid >> 1;        // row-group 0..3
    const int cg   = wid & 1;         // col-group 0..1
    const int g    = lane >> 2;
    const int t    = lane & 3;
    const int row0 = blockIdx.x * 128;

    // bias -> smem (192 floats: K|Q|V)
    if (tid < 192) {
        const float* bsrc = (tid < 64) ? bk : (tid < 128) ? bq : bv;
        ((float*)(sm + SG_BIAS))[tid] = bsrc[tid & 63];
    }

    // ---- precomputed staging-source pointers ----
    const float* asrc[4];
#pragma unroll
    for (int i = 0; i < 4; i++) {
        int f4 = tid + i * 256;       // 0..1023
        int r = f4 >> 3, c4 = f4 & 7;
        asrc[i] = x + (size_t)(row0 + r) * EMBD + c4 * 4;
    }
    const float* bsrc[6];
#pragma unroll
    for (int i = 0; i < 6; i++) {
        int f4 = tid + i * 256;       // 0..1535
        int k = f4 / 48, c4 = f4 % 48;
        int m = c4 >> 4, w4 = c4 & 15;
        const float* W = (m == 0) ? Wk : (m == 1) ? Wq : Wv;
        bsrc[i] = W + (size_t)k * HEAD + w4 * 4;
    }

    float acc[2][12][4];
#pragma unroll
    for (int mt = 0; mt < 2; mt++)
#pragma unroll
        for (int nt = 0; nt < 12; nt++)
#pragma unroll
            for (int j = 0; j < 4; j++) acc[mt][nt][j] = 0.f;

    float4 pa[4], pb[6];

#define LDCHUNK(k0)                                                      \
    do {                                                                 \
        _Pragma("unroll")                                                \
        for (int i = 0; i < 4; i++) pa[i] = *(const float4*)(asrc[i] + (k0)); \
        _Pragma("unroll")                                                \
        for (int i = 0; i < 6; i++) pb[i] = *(const float4*)(bsrc[i] + (size_t)(k0) * HEAD); \
    } while (0)

#define STCHUNK(buf)                                                     \
    do {                                                                 \
        _Pragma("unroll")                                                \
        for (int i = 0; i < 4; i++) {                                    \
            int f4 = tid + i * 256;                                      \
            int r = f4 >> 3, c4 = f4 & 7;                                \
            int ks = c4 >> 1, rl = r & 15;                               \
            int regb = ((c4 & 1) << 1) | (rl >> 3);                      \
            int lbase = (rl & 7) << 2;                                   \
            int region = SG_A(buf) + (((r >> 4) * 4) + ks) * 512;        \
            float e[4] = {tf32_rna(pa[i].x), tf32_rna(pa[i].y),          \
                          tf32_rna(pa[i].z), tf32_rna(pa[i].w)};         \
            _Pragma("unroll")                                            \
            for (int j = 0; j < 4; j++) {                                \
                int l = lbase | j;                                       \
                *(float*)(sm + region + (((l * 16) ^ (ks << 5)) + regb * 4)) = e[j]; \
            }                                                            \
        }                                                                \
        _Pragma("unroll")                                                \
        for (int i = 0; i < 6; i++) {                                    \
            int f4 = tid + i * 256;                                      \
            int k = f4 / 48, c4 = f4 % 48;                               \
            int ks = k >> 3, kin = k & 7;                                \
            int regb = kin >> 2, kin3 = kin & 3;                         \
            int nt = c4 >> 1, nb = (c4 & 1) * 4;                         \
            int bsw = ((nt & 3) << 5) | ((nt >> 2) << 3);                \
            int region = SG_B(buf) + (ks * 24 + nt) * 256;               \
            float e[4] = {tf32_rna(pb[i].x), tf32_rna(pb[i].y),          \
                          tf32_rna(pb[i].z), tf32_rna(pb[i].w)};         \
            _Pragma("unroll")                                            \
            for (int j = 0; j < 4; j++) {                                \
                int l = ((nb + j) << 2) | kin3;                          \
                *(float*)(sm + region + (((l * 8) ^ bsw) + regb * 4)) = e[j]; \
            }                                                            \
        }                                                                \
    } while (0)

    // prologue: chunk 0 staged into buf 0
    LDCHUNK(0);
    STCHUNK(0);
    __syncthreads();

    for (int c = 0; c < NCHNK; ++c) {
        const int buf = c & 1;
        if (c + 1 < NCHNK) LDCHUNK((c + 1) * KCHUNK);

        // ---- MMA on buf ----
#pragma unroll
        for (int ks = 0; ks < 4; ks++) {
            uint4 af[2];
#pragma unroll
            for (int mt = 0; mt < 2; mt++)
                af[mt] = *(const uint4*)(sm + SG_A(buf) + ((rg * 2 + mt) * 4 + ks) * 512 +
                                         ((lane * 16) ^ (ks << 5)));
#pragma unroll
            for (int nt = 0; nt < 12; nt++) {
                int ntg = cg * 12 + nt;
                int bsw = ((ntg & 3) << 5) | ((ntg >> 2) << 3);
                uint2 bf = *(const uint2*)(sm + SG_B(buf) + (ks * 24 + ntg) * 256 +
                                           ((lane * 8) ^ bsw));
#pragma unroll
                for (int mt = 0; mt < 2; mt++)
                    mma_tf32(acc[mt][nt][0], acc[mt][nt][1], acc[mt][nt][2], acc[mt][nt][3],
                             af[mt].x, af[mt].y, af[mt].z, af[mt].w, bf.x, bf.y);
            }
        }

        if (c + 1 < NCHNK) {
            STCHUNK(buf ^ 1);
            __syncthreads();
        }
    }

    // ---- epilogue: +bias, store ----
    const float* sbias = (const float*)(sm + SG_BIAS);
#pragma unroll
    for (int mt = 0; mt < 2; mt++) {
        int r0 = row0 + rg * 32 + mt * 16 + g;
#pragma unroll
        for (int nt = 0; nt < 12; nt++) {
            int ntg = cg * 12 + nt;
            float* out = (ntg < 8) ? g_k : (ntg < 16) ? g_q : g_v;
            int col  = ntg * 8 + t * 2;
            int wcol = col & 63;
            float b0 = sbias[col], b1 = sbias[col + 1];
            *(float2*)&out[(size_t)r0 * HEAD + wcol] =
                make_float2(acc[mt][nt][0] + b0, acc[mt][nt][1] + b1);
            *(float2*)&out[(size_t)(r0 + 8) * HEAD + wcol] =
                make_float2(acc[mt][nt][2] + b0, acc[mt][nt][3] + b1);
        }
    }
#undef LDCHUNK
#undef STCHUNK
}

// ===========================================================================
// Stage 2: flash attention via mma.sync tf32, balanced warps.
// One CTA per batch (256 threads, 8 warps). K/V fragment-packed once.
// Each warp processes TWO m16 query tiles: {wid, 15-wid} -> exactly 5
// 64-key blocks of work per warp (perfect balance).
// ===========================================================================
#define ATT_SMEM (2 * SEQ * HEAD * 4)   // 128KB

__global__ __launch_bounds__(256) void attn_mma(float* __restrict__ out)
{
    extern __shared__ char asm_[];
    float* sKp = (float*)asm_;                       // 64KB
    float* sVp = (float*)(asm_ + SEQ * HEAD * 4);    // 64KB

    const int b    = blockIdx.x;
    const int tid  = threadIdx.x;
    const int wid  = tid >> 5;
    const int lane = tid & 31;
    const int g    = lane >> 2;
    const int t    = lane & 3;

    // ---- cooperative fragment-pack of K and V (tf32-rounded) ----
    const float* kg = g_k + (size_t)b * SEQ * HEAD;
    const float* vg = g_v + (size_t)b * SEQ * HEAD;
    for (int i = tid; i < SEQ * HEAD / 4; i += 256) {
        int s = i >> 4, h4 = i & 15;
        float4 kv = *(const float4*)&kg[s * HEAD + h4 * 4];
        float* rb = sKp + ((s >> 3) * 8 + (h4 >> 1)) * 64 + ((s & 7) << 3) + (h4 & 1);
        rb[0] = tf32_rna(kv.x); rb[2] = tf32_rna(kv.y);
        rb[4] = tf32_rna(kv.z); rb[6] = tf32_rna(kv.w);

        float4 vv = *(const float4*)&vg[s * HEAD + h4 * 4];
        float* rb2 = sVp + ((s >> 3) * 8 + (h4 >> 1)) * 64 + (h4 & 1) * 32 +
                     ((s & 3) << 1) + ((s >> 2) & 1);
        rb2[0]  = tf32_rna(vv.x); rb2[8]  = tf32_rna(vv.y);
        rb2[16] = tf32_rna(vv.z); rb2[24] = tf32_rna(vv.w);
    }
    __syncthreads();

    const int src0 = (lane & ~3) | (t >> 1);
    const int src1 = src0 + 2;

#pragma unroll
    for (int pass = 0; pass < 2; pass++) {
        const int qt = pass ? (15 - wid) : wid;
        const int q0 = qt * 16;
        const int kb_hi = q0 >> 6;

        // Q A-fragments
        const float* qg = g_q + ((size_t)b * SEQ + q0) * HEAD;
        uint32_t qa[8][4];
#pragma unroll
        for (int ks = 0; ks < 8; ks++) {
            qa[ks][0] = __float_as_uint(tf32_rna(qg[(size_t)g * HEAD + ks * 8 + t]));
            qa[ks][1] = __float_as_uint(tf32_rna(qg[(size_t)(g + 8) * HEAD + ks * 8 + t]));
            qa[ks][2] = __float_as_uint(tf32_rna(qg[(size_t)g * HEAD + ks * 8 + t + 4]));
            qa[ks][3] = __float_as_uint(tf32_rna(qg[(size_t)(g + 8) * HEAD + ks * 8 + t + 4]));
        }

        float m0 = -1e30f, m1 = -1e30f, l0 = 0.f, l1 = 0.f;
        float o[8][4];
#pragma unroll
        for (int nf = 0; nf < 8; nf++)
#pragma unroll
            for (int j = 0; j < 4; j++) o[nf][j] = 0.f;

        for (int kb = 0; kb <= kb_hi; kb++) {
            // ---- S = Q K^T ----
            float sacc[8][4];
#pragma unroll
            for (int nf = 0; nf < 8; nf++)
#pragma unroll
                for (int j = 0; j < 4; j++) sacc[nf][j] = 0.f;

#pragma unroll
            for (int ks = 0; ks < 8; ks++) {
                uint2 bf[8];
#pragma unroll
                for (int nf = 0; nf < 8; nf++)
                    bf[nf] = *(const uint2*)(sKp + ((kb * 8 + nf) * 8 + ks) * 64 + lane * 2);
#pragma unroll
                for (int nf = 0; nf < 8; nf++)
                    mma_tf32(sacc[nf][0], sacc[nf][1], sacc[nf][2], sacc[nf][3],
                             qa[ks][0], qa[ks][1], qa[ks][2], qa[ks][3],
                             bf[nf].x, bf[nf].y);
            }

            // ---- scale + causal mask ----
            const float SC = 0.125f;
            if (kb == kb_hi) {
                const int row0 = q0 + g, row1 = row0 + 8;
#pragma unroll
                for (int nf = 0; nf < 8; nf++) {
                    int col = kb * 64 + nf * 8 + 2 * t;
                    sacc[nf][0] = (col     <= row0) ? sacc[nf][0] * SC : -1e30f;
                    sacc[nf][1] = (col + 1 <= row0) ? sacc[nf][1] * SC : -1e30f;
                    sacc[nf][2] = (col     <= row1) ? sacc[nf][2] * SC : -1e30f;
                    sacc[nf][3] = (col + 1 <= row1) ? sacc[nf][3] * SC : -1e30f;
                }
            } else {
#pragma unroll
                for (int nf = 0; nf < 8; nf++)
#pragma unroll
                    for (int j = 0; j < 4; j++) sacc[nf][j] *= SC;
            }

            // ---- online softmax (rows g, g+8) ----
            float mx0 = -1e30f, mx1 = -1e30f;
#pragma unroll
            for (int nf = 0; nf < 8; nf++) {
                mx0 = fmaxf(mx0, fmaxf(sacc[nf][0], sacc[nf][1]));
                mx1 = fmaxf(mx1, fmaxf(sacc[nf][2], sacc[nf][3]));
            }
            mx0 = fmaxf(mx0, __shfl_xor_sync(0xffffffffu, mx0, 1));
            mx0 = fmaxf(mx0, __shfl_xor_sync(0xffffffffu, mx0, 2));
            mx1 = fmaxf(mx1, __shfl_xor_sync(0xffffffffu, mx1, 1));
            mx1 = fmaxf(mx1, __shfl_xor_sync(0xffffffffu, mx1, 2));

            float mn0 = fmaxf(m0, mx0), mn1 = fmaxf(m1, mx1);
            float cr0 = __expf(m0 - mn0), cr1 = __expf(m1 - mn1);
            m0 = mn0; m1 = mn1;

            float s0 = 0.f, s1 = 0.f;
#pragma unroll
            for (int nf = 0; nf < 8; nf++) {
                float p0 = __expf(sacc[nf][0] - m0);
                float p1 = __expf(sacc[nf][1] - m0);
                float p2 = __expf(sacc[nf][2] - m1);
                float p3 = __expf(sacc[nf][3] - m1);
                s0 += p0 + p1; s1 += p2 + p3;
                sacc[nf][0] = tf32_rna(p0); sacc[nf][1] = tf32_rna(p1);
                sacc[nf][2] = tf32_rna(p2); sacc[nf][3] = tf32_rna(p3);
            }
            s0 += __shfl_xor_sync(0xffffffffu, s0, 1);
            s0 += __shfl_xor_sync(0xffffffffu, s0, 2);
            s1 += __shfl_xor_sync(0xffffffffu, s1, 1);
            s1 += __shfl_xor_sync(0xffffffffu, s1, 2);
            l0 = l0 * cr0 + s0;
            l1 = l1 * cr1 + s1;
#pragma unroll
            for (int nf = 0; nf < 8; nf++) {
                o[nf][0] *= cr0; o[nf][1] *= cr0;
                o[nf][2] *= cr1; o[nf][3] *= cr1;
            }

            // ---- O += P V : S-frag -> A-frag via quad shfl, then mma ----
#pragma unroll
            for (int kf = 0; kf < 8; kf++) {
                float v00 = __shfl_sync(0xffffffffu, sacc[kf][0], src0);
                float v01 = __shfl_sync(0xffffffffu, sacc[kf][1], src0);
                float v10 = __shfl_sync(0xffffffffu, sacc[kf][2], src0);
                float v11 = __shfl_sync(0xffffffffu, sacc[kf][3], src0);
                float w00 = __shfl_sync(0xffffffffu, sacc[kf][0], src1);
                float w01 = __shfl_sync(0xffffffffu, sacc[kf][1], src1);
                float w10 = __shfl_sync(0xffffffffu, sacc[kf][2], src1);
                float w11 = __shfl_sync(0xffffffffu, sacc[kf][3], src1);
                uint32_t a0 = __float_as_uint((t & 1) ? v01 : v00);
                uint32_t a1 = __float_as_uint((t & 1) ? v11 : v10);
                uint32_t a2 = __float_as_uint((t & 1) ? w01 : w00);
                uint32_t a3 = __float_as_uint((t & 1) ? w11 : w10);

                uint2 vb[8];
#pragma unroll
                for (int nf = 0; nf < 8; nf++)
                    vb[nf] = *(const uint2*)(sVp + ((kb * 8 + kf) * 8 + nf) * 64 + lane * 2);
#pragma unroll
                for (int nf = 0; nf < 8; nf++)
                    mma_tf32(o[nf][0], o[nf][1], o[nf][2], o[nf][3],
                             a0, a1, a2, a3, vb[nf].x, vb[nf].y);
            }
        }

        // ---- epilogue ----
        const float il0 = 1.f / l0, il1 = 1.f / l1;
        float* og = out + ((size_t)b * SEQ + q0) * HEAD;
#pragma unroll
        for (int nf = 0; nf < 8; nf++) {
            int col = nf * 8 + 2 * t;
            *(float2*)&og[(size_t)g * HEAD + col] =
                make_float2(o[nf][0] * il0, o[nf][1] * il0);
            *(float2*)&og[(size_t)(g + 8) * HEAD + col] =
                make_float2(o[nf][2] * il1, o[nf][3] * il1);
        }
    }
}

// ===========================================================================
extern "C" void kernel_launch(void* const* d_in, const int* in_sizes, int n_in,
                              void* d_out, int out_size)
{
    const float* x  = (const float*)d_in[0];
    const float* Wk = (const float*)d_in[1];
    const float* bk = (const float*)d_in[2];
    const float* Wq = (const float*)d_in[3];
    const float* bq = (const float*)d_in[4];
    const float* Wv = (const float*)d_in[5];
    const float* bv = (const float*)d_in[6];
    float* out = (float*)d_out;
    (void)in_sizes; (void)n_in; (void)out_size;

    cudaFuncSetAttribute(qkv_gemm_mma,
                         cudaFuncAttributeMaxDynamicSharedMemorySize, GEMM_SMEM);
    cudaFuncSetAttribute(attn_mma,
                         cudaFuncAttributeMaxDynamicSharedMemorySize, ATT_SMEM);

    qkv_gemm_mma<<<ROWS / 128, 256, GEMM_SMEM>>>(x, Wk, Wq, Wv, bk, bq, bv);
    attn_mma<<<BATCH, 256, ATT_SMEM>>>(out);
}